// round 14
// baseline (speedup 1.0000x reference)
#include <cuda_runtime.h>
#include <cuda_bf16.h>
#include <cuda_fp16.h>
#include <math.h>
#include <stdint.h>

#define BB 128
#define TT 512
#define EE 300
#define HH 1024
#define H3 3072
#define KEYLEN 15

#define NBLK 128          // persistent blocks (1 per SM)
#define RTH  256          // recurrence threads (8 warps)
#define CHK  128          // K elements per chunk
#define NCH  (HH / CHK)   // 8 chunks per step
#define CHKB 65536        // bytes per packed chunk (hi 32KB + lo 32KB)
#define NSTG 2            // pipeline stages

// recur SMEM layout (dynamic, bytes)
#define SM_WF    0                       // 24 x 1032 fp16 = 49536
#define SM_A     50176                   // 1024-aligned; 2 stages x 65536
#define SM_BIAS  181248                  // 24 floats
#define SM_GATE  181344                  // 8 floats
#define SM_MBAR  181376                  // 2 mbarriers (u64)
#define SM_TOTAL 181504

// keyall SMEM layout (dynamic, bytes)
#define KA_KE    0
#define KA_WSL   18048
#define KA_KXP   116352
#define KA_KH    117792
#define KA_HP    121888
#define KA_TOTAL 122112

typedef unsigned long long ull;

// ---------------- device scratch (static; no cudaMalloc) ------------------------
__device__ float g_xproj[(size_t)BB * TT * H3];        // [t][b][3H]
// hidden state, chunk-packed fp16 + pre-swizzled: [sel][chunk][hi/lo][row][128]
__device__ __align__(1024) __half g_hpk[2][NCH][2][BB][CHK];
__device__ float g_kh[HH];
__device__ float g_gate[HH];
__device__ volatile unsigned g_flags[NBLK];
__device__ volatile unsigned g_kflags[NBLK];

__device__ __forceinline__ float sigm(float v) {
    return __fdividef(1.f, 1.f + __expf(-v));
}
__device__ __forceinline__ float tanh_fast(float x) {
    float e = __expf(2.f * x);
    return 1.f - __fdividef(2.f, e + 1.f);
}

__device__ __forceinline__ void ffma2(ull& d, ull a, ull b) {
    asm("fma.rn.f32x2 %0, %1, %2, %0;" : "+l"(d) : "l"(a), "l"(b));
}
__device__ __forceinline__ float hsum2(ull v) {
    return __int_as_float((unsigned)(v & 0xffffffffull)) + __int_as_float((unsigned)(v >> 32));
}
__device__ __forceinline__ uint32_t smem_to_u32(const void* p) {
    uint32_t a;
    asm("{ .reg .u64 t; cvta.to.shared.u64 t, %1; cvt.u32.u64 %0, t; }" : "=r"(a) : "l"(p));
    return a;
}

#define LDSM_X4(r0, r1, r2, r3, addr) \
    asm volatile("ldmatrix.sync.aligned.m8n8.x4.shared.b16 {%0,%1,%2,%3}, [%4];" \
                 : "=r"(r0), "=r"(r1), "=r"(r2), "=r"(r3) : "r"(addr))

// fp16 MMA, fp32 accumulate; no volatile (pure register op)
#define MMA16816(c, a, b0, b1) \
    asm("mma.sync.aligned.m16n8k16.row.col.f32.f16.f16.f32 " \
        "{%0,%1,%2,%3},{%4,%5,%6,%7},{%8,%9},{%0,%1,%2,%3};" \
        : "+f"((c)[0]), "+f"((c)[1]), "+f"((c)[2]), "+f"((c)[3]) \
        : "r"((a)[0]), "r"((a)[1]), "r"((a)[2]), "r"((a)[3]), "r"(b0), "r"(b1))

#define MBARRIER_INIT(mb, c) \
    asm volatile("mbarrier.init.shared.b64 [%0], %1;" :: "r"((uint32_t)(mb)), "r"((uint32_t)(c)) : "memory")
#define MBAR_ARRIVE_EXPECT(mb, bytes) \
    asm volatile("mbarrier.arrive.expect_tx.shared.b64 _, [%0], %1;" \
                 :: "r"((uint32_t)(mb)), "r"((uint32_t)(bytes)) : "memory")
#define BULK_G2S(dst, src, bytes, mb) \
    asm volatile("cp.async.bulk.shared::cta.global.mbarrier::complete_tx::bytes [%0], [%1], %2, [%3];" \
                 :: "r"((uint32_t)(dst)), "l"(src), "r"((uint32_t)(bytes)), "r"((uint32_t)(mb)) : "memory")
#define MBARRIER_WAIT_PARITY(mb, ph) do { \
    uint32_t _m = (uint32_t)(mb); uint32_t _p = (uint32_t)(ph); uint32_t _d; \
    asm volatile("{\n\t.reg .pred p;\n\t" \
        "mbarrier.try_wait.parity.acquire.cta.shared::cta.b64 p, [%1], %2;\n\t" \
        "selp.b32 %0, 1, 0, p;\n\t}" : "=r"(_d) : "r"(_m), "r"(_p) : "memory"); \
    if (!_d) { \
        asm volatile("{\n\t.reg .pred P1;\n\t" \
            "WL_%=:\n\t" \
            "mbarrier.try_wait.parity.acquire.cta.shared::cta.b64 P1, [%0], %1, 0x989680;\n\t" \
            "@P1 bra.uni WD_%=;\n\tbra.uni WL_%=;\n\tWD_%=:\n\t}" \
            :: "r"(_m), "r"(_p) : "memory"); \
    } } while (0)

// ---------------- init ----------------------------------------------------------
__global__ void zero_kernel() {
    int i = blockIdx.x * blockDim.x + threadIdx.x;
    if (i < (NCH * 2 * BB * CHK) / 2) ((uint32_t*)g_hpk)[i] = 0u;  // zero sel 0
    if (i < HH) g_kh[i] = 0.f;
    if (i < NBLK) { g_flags[i] = 0u; g_kflags[i] = 0u; }
}

__global__ void pad_kernel() {}

// ---------------- xproj (f32x2 scalar GEMM) --------------------------------------
#define XBM 128
#define XBN 64
#define XBK 20
__global__ void xproj_kernel(const int* __restrict__ x, const float* __restrict__ emb,
                             const float* __restrict__ Wih, const float* __restrict__ bih) {
    __shared__ float As[XBM * XBK];
    __shared__ float Bs[XBN * XBK];
    __shared__ int rid[XBM];

    int tid = threadIdx.x;
    int i0 = blockIdx.y * XBM;
    int g0 = blockIdx.x * XBN;

    if (tid < XBM) {
        int i = i0 + tid;
        int t = i / BB, b = i % BB;
        rid[tid] = x[b * TT + t];
    }
    __syncthreads();

    int tx = tid & 15;
    int ty = tid >> 4;

    ull acc[8][4];
#pragma unroll
    for (int r = 0; r < 8; ++r)
#pragma unroll
        for (int c = 0; c < 4; ++c) acc[r][c] = 0ull;

    for (int k0 = 0; k0 < EE; k0 += XBK) {
        for (int idx = tid; idx < XBM * XBK; idx += 256) {
            int row = idx / XBK, kk = idx % XBK;
            As[row * XBK + kk] = emb[(size_t)rid[row] * EE + k0 + kk];
        }
        for (int idx = tid; idx < XBN * XBK; idx += 256) {
            int c = idx / XBK, kk = idx % XBK;
            Bs[c * XBK + kk] = Wih[(size_t)(g0 + c) * EE + k0 + kk];
        }
        __syncthreads();
#pragma unroll
        for (int kp = 0; kp < XBK / 2; ++kp) {
            ull bv[4];
#pragma unroll
            for (int c = 0; c < 4; ++c)
                bv[c] = *(const ull*)(Bs + (tx * 4 + c) * XBK + 2 * kp);
#pragma unroll
            for (int r = 0; r < 8; ++r) {
                ull av = *(const ull*)(As + (ty * 8 + r) * XBK + 2 * kp);
#pragma unroll
                for (int c = 0; c < 4; ++c) ffma2(acc[r][c], av, bv[c]);
            }
        }
        __syncthreads();
    }
#pragma unroll
    for (int r = 0; r < 8; ++r) {
        size_t i = (size_t)(i0 + ty * 8 + r);
#pragma unroll
        for (int c = 0; c < 4; ++c) {
            int g = g0 + tx * 4 + c;
            g_xproj[i * H3 + g] = hsum2(acc[r][c]) + bih[g];
        }
    }
}

// ---------------- barriers -------------------------------------------------------
__device__ __forceinline__ void grid_barrier(unsigned target) {
    __syncthreads();
    if (threadIdx.x == 0) {
        __threadfence();
        g_flags[blockIdx.x] = target;
    }
    if (threadIdx.x < NBLK) {
        while (g_flags[threadIdx.x] < target) { }
    }
    __syncthreads();
}
__device__ __forceinline__ void kgrid_barrier(unsigned target) {
    __syncthreads();
    if (threadIdx.x == 0) {
        __threadfence();
        g_kflags[blockIdx.x] = target;
    }
    if (threadIdx.x < NBLK) {
        while (g_kflags[threadIdx.x] < target) { }
    }
    __syncthreads();
}

// ---------------- fused key-GRU kernel -------------------------------------------
__global__ void __launch_bounds__(256, 1)
keyall_kernel(const int* __restrict__ key_ids, const float* __restrict__ emb,
              const float* __restrict__ Wih, const float* __restrict__ Whh,
              const float* __restrict__ bih, const float* __restrict__ bhh,
              const float* __restrict__ Wg, const float* __restrict__ bg) {
    extern __shared__ char smem[];
    float* ke    = (float*)(smem + KA_KE);
    float* Wsl   = (float*)(smem + KA_WSL);
    float* kxp_s = (float*)(smem + KA_KXP);
    float* kh_s  = (float*)(smem + KA_KH);
    float* hp_s  = (float*)(smem + KA_HP);

    int tid = threadIdx.x;
    int lane = tid & 31, w = tid >> 5;
    int j0 = blockIdx.x * 8;

    for (int i = tid; i < KEYLEN * EE; i += 256) {
        int t = i / EE, e = i % EE;
        ke[i] = emb[(size_t)key_ids[t] * EE + e];
    }
    for (int i = tid; i < 24 * HH; i += 256) {
        int n = i >> 10, k = i & 1023;
        Wsl[i] = Whh[(size_t)((n >> 3) * HH + j0 + (n & 7)) * HH + k];
    }
    __syncthreads();

    for (int i = tid; i < KEYLEN * 24; i += 256) {
        int t = i / 24, n = i % 24;
        int grow = (n >> 3) * HH + j0 + (n & 7);
        const float* wr = Wih + (size_t)grow * EE;
        float acc = 0.f;
        for (int e = 0; e < EE; ++e) acc += wr[e] * ke[t * EE + e];
        kxp_s[i] = acc + bih[grow];
    }
    __syncthreads();

    for (int t = 0; t < KEYLEN; ++t) {
        for (int i = tid; i < HH; i += 256) kh_s[i] = __ldcg(&g_kh[i]);
        __syncthreads();
#pragma unroll
        for (int rr = 0; rr < 3; ++rr) {
            int n = w * 3 + rr;
            const float* wr = Wsl + n * HH;
            float a = 0.f;
            for (int k = lane; k < HH; k += 32) a += wr[k] * kh_s[k];
#pragma unroll
            for (int o = 16; o; o >>= 1) a += __shfl_xor_sync(0xffffffffu, a, o);
            if (lane == 0) hp_s[n] = a;
        }
        __syncthreads();
        if (tid < 8) {
            int j = j0 + tid;
            float r = sigm(kxp_s[t * 24 + tid] + hp_s[tid] + bhh[j]);
            float z = sigm(kxp_s[t * 24 + 8 + tid] + hp_s[8 + tid] + bhh[HH + j]);
            float n2 = tanh_fast(kxp_s[t * 24 + 16 + tid] + r * (hp_s[16 + tid] + bhh[2 * HH + j]));
            g_kh[j] = (1.f - z) * n2 + z * kh_s[j];
        }
        kgrid_barrier((unsigned)(t + 1));
    }

    for (int i = tid; i < HH; i += 256) kh_s[i] = __ldcg(&g_kh[i]);
    __syncthreads();
    {
        int j = j0 + w;
        const float* wr = Wg + (size_t)j * HH;
        float a = 0.f;
        for (int k = lane; k < HH; k += 32) a += wr[k] * kh_s[k];
#pragma unroll
        for (int o = 16; o; o >>= 1) a += __shfl_xor_sync(0xffffffffu, a, o);
        if (lane == 0) g_gate[j] = sigm(a + bg[j]);
    }
}

// ---------------- persistent HMMA recurrence (fp16 hi/lo 2-pass) -----------------
// 128 blocks x 256 threads. W_hh slice in SMEM as SINGLE fp16 (24 rows). Hidden
// state chunk-packed fp16 hi/lo (8 chunks of K=128), staged via 2-stage 64KB
// cp.async.bulk. Per k-step: 2 MMA passes (h_hi*W + h_lo*W), fp32 accumulate.
__global__ void __launch_bounds__(RTH, 1)
recur_kernel(const float* __restrict__ Whh, const float* __restrict__ bhh,
             float* __restrict__ out) {
    extern __shared__ char smem[];
    uint32_t smem_base = smem_to_u32(smem);
    float* bias_s = (float*)(smem + SM_BIAS);
    float* gate_s = (float*)(smem + SM_GATE);
    __half* wf_s = (__half*)(smem + SM_WF);

    int tid = threadIdx.x;
    int lane = tid & 31;
    int w = tid >> 5;
    int j0 = blockIdx.x * 8;

    if (tid == 0) {
#pragma unroll
        for (int s = 0; s < NSTG; ++s) MBARRIER_INIT(smem_base + SM_MBAR + s * 8, 1);
    }
    asm volatile("fence.proxy.async.shared::cta;" ::: "memory");

    // W_hh slice: rows n = gate*8 + cj, k-contiguous fp16, row stride 1032
    for (int idx = tid; idx < 24 * HH; idx += RTH) {
        int n = idx >> 10, k = idx & (HH - 1);
        float f = Whh[(size_t)((n >> 3) * HH + j0 + (n & 7)) * HH + k];
        wf_s[n * 1032 + k] = __float2half_rn(f);
    }
    if (tid < 24) bias_s[tid] = bhh[(tid >> 3) * HH + j0 + (tid & 7)];
    if (tid < 8)  gate_s[tid] = g_gate[j0 + tid];
    __syncthreads();

    // fragment geometry
    int arow = 16 * w + (lane & 15);        // A row for ldmatrix
    int ar7 = arow & 7;
    uint32_t arowb = (uint32_t)(arow * 256); // 128 fp16 = 256 B per row
    int lhalf = lane >> 4;
    uint32_t b_off[3];
#pragma unroll
    for (int nt = 0; nt < 3; ++nt)
        b_off[nt] = (uint32_t)((nt * 8 + (lane & 7)) * 2064 + (lane >> 3) * 16);

    int row0 = 16 * w + (lane >> 2);        // epilogue rows row0, row0+8
    int jc = 2 * (lane & 3);                // col pair within 8
    float gv = gate_s[jc], gv1 = gate_s[jc + 1];
    float b_r0 = bias_s[jc],      b_r1 = bias_s[jc + 1];
    float b_z0 = bias_s[8 + jc],  b_z1 = bias_s[8 + jc + 1];
    float b_n0 = bias_s[16 + jc], b_n1 = bias_s[16 + jc + 1];

    // packed-h addressing for this block's columns (chunk = j0>>7)
    int mychunk = j0 >> 7;
    int cw = (j0 & 127) + jc;               // within-chunk col (pairs stay in one 16B group)
    uint32_t g0u = (uint32_t)(cw >> 3);
    uint32_t ep0 = (uint32_t)(row0 * 256 + (((g0u ^ (uint32_t)(row0 & 7)) << 4)) + ((cw * 2) & 15));
    int row1 = row0 + 8;
    uint32_t ep1 = (uint32_t)(row1 * 256 + (((g0u ^ (uint32_t)(row1 & 7)) << 4)) + ((cw * 2) & 15));

    unsigned phbits = 0;
    int stg = 0;

#pragma unroll 1
    for (int t = 0; t < TT; ++t) {
        int sel = t & 1;
        const char* hsrc = (const char*)&g_hpk[sel][0][0][0][0];
        char* hdst = (char*)&g_hpk[sel ^ 1][0][0][0][0];
        const float* xp = g_xproj + (size_t)t * BB * H3;

        if (tid == 0) {
            int s = stg;
#pragma unroll
            for (int p = 0; p < NSTG; ++p) {
                uint32_t mb = smem_base + SM_MBAR + s * 8;
                MBAR_ARRIVE_EXPECT(mb, CHKB);
                BULK_G2S(smem_base + SM_A + s * CHKB, hsrc + (size_t)p * CHKB, CHKB, mb);
                s ^= 1;
            }
        }

        const float* xpr0 = xp + (size_t)row0 * H3 + j0 + jc;
        const float* xpr1 = xp + (size_t)row1 * H3 + j0 + jc;
        float2 xr0 = __ldcs((const float2*)(xpr0));
        float2 xz0 = __ldcs((const float2*)(xpr0 + HH));
        float2 xn0 = __ldcs((const float2*)(xpr0 + 2 * HH));
        float2 xr1 = __ldcs((const float2*)(xpr1));
        float2 xz1 = __ldcs((const float2*)(xpr1 + HH));
        float2 xn1 = __ldcs((const float2*)(xpr1 + 2 * HH));
        const char* hcs = hsrc + (size_t)mychunk * CHKB;
        __half2 hh0 = *(const __half2*)(hcs + ep0);
        __half2 hl0 = *(const __half2*)(hcs + 32768 + ep0);
        __half2 hh1 = *(const __half2*)(hcs + ep1);
        __half2 hl1 = *(const __half2*)(hcs + 32768 + ep1);
        float hold00 = __low2float(hh0) + __low2float(hl0);
        float hold01 = __high2float(hh0) + __high2float(hl0);
        float hold10 = __low2float(hh1) + __low2float(hl1);
        float hold11 = __high2float(hh1) + __high2float(hl1);

        // 6 accumulators: [ntile][k-parity]
        float cacc[3][2][4];
#pragma unroll
        for (int nt = 0; nt < 3; ++nt)
#pragma unroll
            for (int s = 0; s < 2; ++s)
#pragma unroll
                for (int i = 0; i < 4; ++i) cacc[nt][s][i] = 0.f;

#pragma unroll 1
        for (int c = 0; c < NCH; ++c) {
            uint32_t mb = smem_base + SM_MBAR + stg * 8;
            MBARRIER_WAIT_PARITY(mb, (phbits >> stg) & 1);
            phbits ^= (1u << stg);

            uint32_t sbase = smem_base + SM_A + (uint32_t)(stg * CHKB) + arowb;
#pragma unroll
            for (int s2 = 0; s2 < 4; ++s2) {
                // B fragments: single fp16 W, 3 n-tiles, k32
                uint32_t bf[3][4];
#pragma unroll
                for (int nt = 0; nt < 3; ++nt) {
                    uint32_t bb = smem_base + b_off[nt] + (uint32_t)((c * 4 + s2) * 64);
                    LDSM_X4(bf[nt][0], bf[nt][1], bf[nt][2], bf[nt][3], bb + SM_WF);
                }
                // A fragments for both k-steps, hi and lo arrays
                uint32_t ah[2][4], al[2][4];
#pragma unroll
                for (int s = 0; s < 2; ++s) {
                    int u = s2 * 4 + s * 2 + lhalf;
                    uint32_t aa = sbase + (uint32_t)(((u ^ ar7)) << 4);
                    LDSM_X4(ah[s][0], ah[s][1], ah[s][2], ah[s][3], aa);
                    LDSM_X4(al[s][0], al[s][1], al[s][2], al[s][3], aa + 32768);
                }
                // 12 MMAs, same-accumulator distance = 6
#pragma unroll
                for (int s = 0; s < 2; ++s)
#pragma unroll
                    for (int nt = 0; nt < 3; ++nt)
                        MMA16816(cacc[nt][s], ah[s], bf[nt][2 * s], bf[nt][2 * s + 1]);
#pragma unroll
                for (int s = 0; s < 2; ++s)
#pragma unroll
                    for (int nt = 0; nt < 3; ++nt)
                        MMA16816(cacc[nt][s], al[s], bf[nt][2 * s], bf[nt][2 * s + 1]);
            }
            __syncthreads();

            if (c + NSTG < NCH && tid == 0) {
                MBAR_ARRIVE_EXPECT(mb, CHKB);
                BULK_G2S(smem_base + SM_A + (uint32_t)(stg * CHKB),
                         hsrc + (size_t)(c + NSTG) * CHKB, CHKB, mb);
            }
            stg ^= 1;
        }

        // merge k-parity accumulators
        float cfin[3][4];
#pragma unroll
        for (int nt = 0; nt < 3; ++nt)
#pragma unroll
            for (int i = 0; i < 4; ++i) cfin[nt][i] = cacc[nt][0][i] + cacc[nt][1][i];

        char* hcd = hdst + (size_t)mychunk * CHKB;
#pragma unroll
        for (int half = 0; half < 2; ++half) {
            int row = half ? row1 : row0;
            int ib = 2 * half;
            float xr_ = half ? xr1.x : xr0.x, xr_1 = half ? xr1.y : xr0.y;
            float xz_ = half ? xz1.x : xz0.x, xz_1 = half ? xz1.y : xz0.y;
            float xn_ = half ? xn1.x : xn0.x, xn_1 = half ? xn1.y : xn0.y;
            float ho0 = half ? hold10 : hold00;
            float ho1 = half ? hold11 : hold01;

            float rg0 = sigm(xr_ + cfin[0][ib] + b_r0);
            float zg0 = sigm(xz_ + cfin[1][ib] + b_z0);
            float ng0 = tanh_fast(xn_ + rg0 * (cfin[2][ib] + b_n0));
            float o0 = gv * ((1.f - zg0) * ng0 + zg0 * ho0);

            float rg1 = sigm(xr_1 + cfin[0][ib + 1] + b_r1);
            float zg1 = sigm(xz_1 + cfin[1][ib + 1] + b_z1);
            float ng1 = tanh_fast(xn_1 + rg1 * (cfin[2][ib + 1] + b_n1));
            float o1 = gv1 * ((1.f - zg1) * ng1 + zg1 * ho1);

            if (t == TT - 1) {
                *(float2*)(out + (size_t)row * HH + j0 + jc) = make_float2(o0, o1);
            } else {
                __half h0 = __float2half_rn(o0);
                __half h1 = __float2half_rn(o1);
                __half2 hv; hv.x = h0; hv.y = h1;
                __half2 lv;
                lv.x = __float2half_rn(o0 - __half2float(h0));
                lv.y = __float2half_rn(o1 - __half2float(h1));
                uint32_t ep = half ? ep1 : ep0;
                *(__half2*)(hcd + ep) = hv;
                *(__half2*)(hcd + 32768 + ep) = lv;
            }
        }

        if (t < TT - 1) grid_barrier((unsigned)(t + 1));
    }
}

// ---------------- launch ---------------------------------------------------------
extern "C" void kernel_launch(void* const* d_in, const int* in_sizes, int n_in,
                              void* d_out, int out_size) {
    const int* x        = (const int*)d_in[0];
    const int* key_ids  = (const int*)d_in[1];
    const float* emb    = (const float*)d_in[2];
    const float* W_ih   = (const float*)d_in[3];
    const float* W_hh   = (const float*)d_in[4];
    const float* b_ih   = (const float*)d_in[5];
    const float* b_hh   = (const float*)d_in[6];
    const float* W_g    = (const float*)d_in[7];
    const float* b_g    = (const float*)d_in[8];
    float* out = (float*)d_out;

    cudaFuncSetAttribute(recur_kernel, cudaFuncAttributeMaxDynamicSharedMemorySize, SM_TOTAL);
    cudaFuncSetAttribute(keyall_kernel, cudaFuncAttributeMaxDynamicSharedMemorySize, KA_TOTAL);

    zero_kernel<<<(BB * HH + 255) / 256, 256>>>();                               // 0
    keyall_kernel<<<NBLK, 256, KA_TOTAL>>>(key_ids, emb, W_ih, W_hh,
                                           b_ih, b_hh, W_g, b_g);                // 1
    dim3 xg(H3 / XBN, (BB * TT) / XBM);
    xproj_kernel<<<xg, 256>>>(x, emb, W_ih, b_ih);                               // 2
    pad_kernel<<<1, 32>>>();                                                     // 3
    pad_kernel<<<1, 32>>>();                                                     // 4
    recur_kernel<<<NBLK, RTH, SM_TOTAL>>>(W_hh, b_hh, out);                      // 5
}

// round 15
// speedup vs baseline: 1.0284x; 1.0284x over previous
#include <cuda_runtime.h>
#include <cuda_bf16.h>
#include <math.h>
#include <stdint.h>

#define BB 128
#define TT 512
#define EE 300
#define HH 1024
#define H3 3072
#define KEYLEN 15

#define NBLK 128          // persistent blocks (1 per SM)
#define RTH  256          // recurrence threads (8 warps)
#define CHK  64           // K elements per chunk
#define NCH  (HH / CHK)   // 16 chunks per step
#define CHKB 32768        // bytes per packed chunk (hi 16KB + lo 16KB)
#define NSTG 3            // pipeline stages
#define NPROD 8           // producer blocks per chunk (64 cols / 8 cols)

// recur SMEM layout (dynamic, bytes)
#define SM_WHI   0                       // 24 x 1032 bf16 = 49536
#define SM_WLO   49536                   // 49536
#define SM_A     99328                   // 1024-aligned; 3 stages x 32768
#define SM_BIAS  197632                  // 24 floats
#define SM_GATE  197728                  // 8 floats
#define SM_MBAR  197760                  // 3 mbarriers (u64)
#define SM_TOTAL 197888

// keyall SMEM layout (dynamic, bytes)
#define KA_KE    0
#define KA_WSL   18048
#define KA_KXP   116352
#define KA_KH    117792
#define KA_HP    121888
#define KA_TOTAL 122112

typedef unsigned long long ull;

// ---------------- device scratch (static; no cudaMalloc) ------------------------
__device__ float g_xproj[(size_t)BB * TT * H3];        // [t][b][3H]
// hidden state, chunk-packed + pre-swizzled: [sel][chunk][hi/lo][row][64] bf16
__device__ __align__(1024) __nv_bfloat16 g_hpk[2][NCH][2][BB][CHK];
__device__ float g_kh[HH];
__device__ float g_gate[HH];
__device__ unsigned g_cnt[NCH];           // per-chunk production counters
__device__ volatile unsigned g_kflags[NBLK];

__device__ __forceinline__ float sigm(float v) {
    return __fdividef(1.f, 1.f + __expf(-v));
}
__device__ __forceinline__ float tanh_fast(float x) {
    float e = __expf(2.f * x);
    return 1.f - __fdividef(2.f, e + 1.f);
}

__device__ __forceinline__ void ffma2(ull& d, ull a, ull b) {
    asm("fma.rn.f32x2 %0, %1, %2, %0;" : "+l"(d) : "l"(a), "l"(b));
}
__device__ __forceinline__ float hsum2(ull v) {
    return __int_as_float((unsigned)(v & 0xffffffffull)) + __int_as_float((unsigned)(v >> 32));
}
__device__ __forceinline__ uint32_t smem_to_u32(const void* p) {
    uint32_t a;
    asm("{ .reg .u64 t; cvta.to.shared.u64 t, %1; cvt.u32.u64 %0, t; }" : "=r"(a) : "l"(p));
    return a;
}
__device__ __forceinline__ unsigned ld_acq(const unsigned* p) {
    unsigned v;
    asm volatile("ld.global.acquire.gpu.u32 %0, [%1];" : "=r"(v) : "l"(p));
    return v;
}

#define LDSM_X4(r0, r1, r2, r3, addr) \
    asm volatile("ldmatrix.sync.aligned.m8n8.x4.shared.b16 {%0,%1,%2,%3}, [%4];" \
                 : "=r"(r0), "=r"(r1), "=r"(r2), "=r"(r3) : "r"(addr))

#define MMA16816(c, a, b0, b1) \
    asm("mma.sync.aligned.m16n8k16.row.col.f32.bf16.bf16.f32 " \
        "{%0,%1,%2,%3},{%4,%5,%6,%7},{%8,%9},{%0,%1,%2,%3};" \
        : "+f"((c)[0]), "+f"((c)[1]), "+f"((c)[2]), "+f"((c)[3]) \
        : "r"((a)[0]), "r"((a)[1]), "r"((a)[2]), "r"((a)[3]), "r"(b0), "r"(b1))

#define MBARRIER_INIT(mb, c) \
    asm volatile("mbarrier.init.shared.b64 [%0], %1;" :: "r"((uint32_t)(mb)), "r"((uint32_t)(c)) : "memory")
#define MBAR_ARRIVE_EXPECT(mb, bytes) \
    asm volatile("mbarrier.arrive.expect_tx.shared.b64 _, [%0], %1;" \
                 :: "r"((uint32_t)(mb)), "r"((uint32_t)(bytes)) : "memory")
#define BULK_G2S(dst, src, bytes, mb) \
    asm volatile("cp.async.bulk.shared::cta.global.mbarrier::complete_tx::bytes [%0], [%1], %2, [%3];" \
                 :: "r"((uint32_t)(dst)), "l"(src), "r"((uint32_t)(bytes)), "r"((uint32_t)(mb)) : "memory")
#define MBARRIER_WAIT_PARITY(mb, ph) do { \
    uint32_t _m = (uint32_t)(mb); uint32_t _p = (uint32_t)(ph); uint32_t _d; \
    asm volatile("{\n\t.reg .pred p;\n\t" \
        "mbarrier.try_wait.parity.acquire.cta.shared::cta.b64 p, [%1], %2;\n\t" \
        "selp.b32 %0, 1, 0, p;\n\t}" : "=r"(_d) : "r"(_m), "r"(_p) : "memory"); \
    if (!_d) { \
        asm volatile("{\n\t.reg .pred P1;\n\t" \
            "WL_%=:\n\t" \
            "mbarrier.try_wait.parity.acquire.cta.shared::cta.b64 P1, [%0], %1, 0x989680;\n\t" \
            "@P1 bra.uni WD_%=;\n\tbra.uni WL_%=;\n\tWD_%=:\n\t}" \
            :: "r"(_m), "r"(_p) : "memory"); \
    } } while (0)

// ---------------- init ----------------------------------------------------------
__global__ void zero_kernel() {
    int i = blockIdx.x * blockDim.x + threadIdx.x;
    if (i < (NCH * 2 * BB * CHK) / 2) ((uint32_t*)g_hpk)[i] = 0u;  // zero sel 0
    if (i < HH) g_kh[i] = 0.f;
    if (i < NCH) g_cnt[i] = 0u;
    if (i < NBLK) g_kflags[i] = 0u;
}

__global__ void pad_kernel() {}

// ---------------- xproj (f32x2 scalar GEMM) --------------------------------------
#define XBM 128
#define XBN 64
#define XBK 20
__global__ void xproj_kernel(const int* __restrict__ x, const float* __restrict__ emb,
                             const float* __restrict__ Wih, const float* __restrict__ bih) {
    __shared__ float As[XBM * XBK];
    __shared__ float Bs[XBN * XBK];
    __shared__ int rid[XBM];

    int tid = threadIdx.x;
    int i0 = blockIdx.y * XBM;
    int g0 = blockIdx.x * XBN;

    if (tid < XBM) {
        int i = i0 + tid;
        int t = i / BB, b = i % BB;
        rid[tid] = x[b * TT + t];
    }
    __syncthreads();

    int tx = tid & 15;
    int ty = tid >> 4;

    ull acc[8][4];
#pragma unroll
    for (int r = 0; r < 8; ++r)
#pragma unroll
        for (int c = 0; c < 4; ++c) acc[r][c] = 0ull;

    for (int k0 = 0; k0 < EE; k0 += XBK) {
        for (int idx = tid; idx < XBM * XBK; idx += 256) {
            int row = idx / XBK, kk = idx % XBK;
            As[row * XBK + kk] = emb[(size_t)rid[row] * EE + k0 + kk];
        }
        for (int idx = tid; idx < XBN * XBK; idx += 256) {
            int c = idx / XBK, kk = idx % XBK;
            Bs[c * XBK + kk] = Wih[(size_t)(g0 + c) * EE + k0 + kk];
        }
        __syncthreads();
#pragma unroll
        for (int kp = 0; kp < XBK / 2; ++kp) {
            ull bv[4];
#pragma unroll
            for (int c = 0; c < 4; ++c)
                bv[c] = *(const ull*)(Bs + (tx * 4 + c) * XBK + 2 * kp);
#pragma unroll
            for (int r = 0; r < 8; ++r) {
                ull av = *(const ull*)(As + (ty * 8 + r) * XBK + 2 * kp);
#pragma unroll
                for (int c = 0; c < 4; ++c) ffma2(acc[r][c], av, bv[c]);
            }
        }
        __syncthreads();
    }
#pragma unroll
    for (int r = 0; r < 8; ++r) {
        size_t i = (size_t)(i0 + ty * 8 + r);
#pragma unroll
        for (int c = 0; c < 4; ++c) {
            int g = g0 + tx * 4 + c;
            g_xproj[i * H3 + g] = hsum2(acc[r][c]) + bih[g];
        }
    }
}

// ---------------- keyall grid barrier --------------------------------------------
__device__ __forceinline__ void kgrid_barrier(unsigned target) {
    __syncthreads();
    if (threadIdx.x == 0) {
        __threadfence();
        g_kflags[blockIdx.x] = target;
    }
    if (threadIdx.x < NBLK) {
        while (g_kflags[threadIdx.x] < target) { }
    }
    __syncthreads();
}

// ---------------- fused key-GRU kernel -------------------------------------------
__global__ void __launch_bounds__(256, 1)
keyall_kernel(const int* __restrict__ key_ids, const float* __restrict__ emb,
              const float* __restrict__ Wih, const float* __restrict__ Whh,
              const float* __restrict__ bih, const float* __restrict__ bhh,
              const float* __restrict__ Wg, const float* __restrict__ bg) {
    extern __shared__ char smem[];
    float* ke    = (float*)(smem + KA_KE);
    float* Wsl   = (float*)(smem + KA_WSL);
    float* kxp_s = (float*)(smem + KA_KXP);
    float* kh_s  = (float*)(smem + KA_KH);
    float* hp_s  = (float*)(smem + KA_HP);

    int tid = threadIdx.x;
    int lane = tid & 31, w = tid >> 5;
    int j0 = blockIdx.x * 8;

    for (int i = tid; i < KEYLEN * EE; i += 256) {
        int t = i / EE, e = i % EE;
        ke[i] = emb[(size_t)key_ids[t] * EE + e];
    }
    for (int i = tid; i < 24 * HH; i += 256) {
        int n = i >> 10, k = i & 1023;
        Wsl[i] = Whh[(size_t)((n >> 3) * HH + j0 + (n & 7)) * HH + k];
    }
    __syncthreads();

    for (int i = tid; i < KEYLEN * 24; i += 256) {
        int t = i / 24, n = i % 24;
        int grow = (n >> 3) * HH + j0 + (n & 7);
        const float* wr = Wih + (size_t)grow * EE;
        float acc = 0.f;
        for (int e = 0; e < EE; ++e) acc += wr[e] * ke[t * EE + e];
        kxp_s[i] = acc + bih[grow];
    }
    __syncthreads();

    for (int t = 0; t < KEYLEN; ++t) {
        for (int i = tid; i < HH; i += 256) kh_s[i] = __ldcg(&g_kh[i]);
        __syncthreads();
#pragma unroll
        for (int rr = 0; rr < 3; ++rr) {
            int n = w * 3 + rr;
            const float* wr = Wsl + n * HH;
            float a = 0.f;
            for (int k = lane; k < HH; k += 32) a += wr[k] * kh_s[k];
#pragma unroll
            for (int o = 16; o; o >>= 1) a += __shfl_xor_sync(0xffffffffu, a, o);
            if (lane == 0) hp_s[n] = a;
        }
        __syncthreads();
        if (tid < 8) {
            int j = j0 + tid;
            float r = sigm(kxp_s[t * 24 + tid] + hp_s[tid] + bhh[j]);
            float z = sigm(kxp_s[t * 24 + 8 + tid] + hp_s[8 + tid] + bhh[HH + j]);
            float n2 = tanh_fast(kxp_s[t * 24 + 16 + tid] + r * (hp_s[16 + tid] + bhh[2 * HH + j]));
            g_kh[j] = (1.f - z) * n2 + z * kh_s[j];
        }
        kgrid_barrier((unsigned)(t + 1));
    }

    for (int i = tid; i < HH; i += 256) kh_s[i] = __ldcg(&g_kh[i]);
    __syncthreads();
    {
        int j = j0 + w;
        const float* wr = Wg + (size_t)j * HH;
        float a = 0.f;
        for (int k = lane; k < HH; k += 32) a += wr[k] * kh_s[k];
#pragma unroll
        for (int o = 16; o; o >>= 1) a += __shfl_xor_sync(0xffffffffu, a, o);
        if (lane == 0) g_gate[j] = sigm(a + bg[j]);
    }
}

// ---------------- persistent HMMA recurrence (per-chunk dataflow sync) -----------
// 128 blocks x 256 threads. Rigid grid barrier replaced by per-chunk counters:
// 8 producer blocks per 64-col chunk bump g_cnt[c] after their epilogue; consumer
// tid0 gates each chunk's bulk copy on cnt[c] >= 8*t. Fast blocks flow into the
// next step while stragglers finish - skew absorbed chunk-by-chunk.
__global__ void __launch_bounds__(RTH, 1)
recur_kernel(const float* __restrict__ Whh, const float* __restrict__ bhh,
             float* __restrict__ out) {
    extern __shared__ char smem[];
    uint32_t smem_base = smem_to_u32(smem);
    float* bias_s = (float*)(smem + SM_BIAS);
    float* gate_s = (float*)(smem + SM_GATE);
    __nv_bfloat16* whi_s = (__nv_bfloat16*)(smem + SM_WHI);
    __nv_bfloat16* wlo_s = (__nv_bfloat16*)(smem + SM_WLO);

    int tid = threadIdx.x;
    int lane = tid & 31;
    int w = tid >> 5;
    int j0 = blockIdx.x * 8;

    if (tid == 0) {
#pragma unroll
        for (int s = 0; s < NSTG; ++s) MBARRIER_INIT(smem_base + SM_MBAR + s * 8, 1);
    }
    asm volatile("fence.proxy.async.shared::cta;" ::: "memory");

    for (int idx = tid; idx < 24 * HH; idx += RTH) {
        int n = idx >> 10, k = idx & (HH - 1);
        float f = Whh[(size_t)((n >> 3) * HH + j0 + (n & 7)) * HH + k];
        __nv_bfloat16 hi = __float2bfloat16_rn(f);
        __nv_bfloat16 lo = __float2bfloat16_rn(f - __bfloat162float(hi));
        whi_s[n * 1032 + k] = hi;
        wlo_s[n * 1032 + k] = lo;
    }
    if (tid < 24) bias_s[tid] = bhh[(tid >> 3) * HH + j0 + (tid & 7)];
    if (tid < 8)  gate_s[tid] = g_gate[j0 + tid];
    __syncthreads();

    // fragment geometry
    int arow = 16 * w + (lane & 15);
    int ar7 = arow & 7;
    uint32_t arowb = (uint32_t)(arow * 128);
    int lhalf = lane >> 4;
    uint32_t b_off[3];
#pragma unroll
    for (int nt = 0; nt < 3; ++nt)
        b_off[nt] = (uint32_t)((nt * 8 + (lane & 7)) * 2064 + (lane >> 3) * 16);

    int row0 = 16 * w + (lane >> 2);
    int jc = 2 * (lane & 3);
    float gv = gate_s[jc], gv1 = gate_s[jc + 1];
    float b_r0 = bias_s[jc],      b_r1 = bias_s[jc + 1];
    float b_z0 = bias_s[8 + jc],  b_z1 = bias_s[8 + jc + 1];
    float b_n0 = bias_s[16 + jc], b_n1 = bias_s[16 + jc + 1];

    int mychunk = j0 >> 6;
    int cw = (j0 & 63) + jc;
    uint32_t ep0 = (uint32_t)(((row0 * 128 + cw * 2) ^ ((row0 & 7) << 4)));
    uint32_t ep1 = (uint32_t)((((row0 + 8) * 128 + cw * 2) ^ (((row0 + 8) & 7) << 4)));

    unsigned phbits = 0;
    int stg = 0;

#pragma unroll 1
    for (int t = 0; t < TT; ++t) {
        int sel = t & 1;
        const char* hsrc = (const char*)&g_hpk[sel][0][0][0][0];
        char* hdst = (char*)&g_hpk[sel ^ 1][0][0][0][0];
        const float* xp = g_xproj + (size_t)t * BB * H3;
        unsigned tgt = (unsigned)(NPROD * t);

        // prologue: fill the pipeline (each copy gated on its chunk's producers)
        if (tid == 0) {
            int s = stg;
#pragma unroll
            for (int p = 0; p < NSTG; ++p) {
                while (ld_acq(&g_cnt[p]) < tgt) { }
                uint32_t mb = smem_base + SM_MBAR + s * 8;
                MBAR_ARRIVE_EXPECT(mb, CHKB);
                BULK_G2S(smem_base + SM_A + s * CHKB, hsrc + (size_t)p * CHKB, CHKB, mb);
                s = (s + 1 == NSTG) ? 0 : s + 1;
            }
        }

        // prefetch epilogue x-projections (independent of h)
        const float* xpr0 = xp + (size_t)row0 * H3 + j0 + jc;
        const float* xpr1 = xp + (size_t)(row0 + 8) * H3 + j0 + jc;
        float2 xr0 = __ldcs((const float2*)(xpr0));
        float2 xz0 = __ldcs((const float2*)(xpr0 + HH));
        float2 xn0 = __ldcs((const float2*)(xpr0 + 2 * HH));
        float2 xr1 = __ldcs((const float2*)(xpr1));
        float2 xz1 = __ldcs((const float2*)(xpr1 + HH));
        float2 xn1 = __ldcs((const float2*)(xpr1 + 2 * HH));
        float hold00 = 0.f, hold01 = 0.f, hold10 = 0.f, hold11 = 0.f;

        float cacc[3][2][4];
#pragma unroll
        for (int nt = 0; nt < 3; ++nt)
#pragma unroll
            for (int s = 0; s < 2; ++s)
#pragma unroll
                for (int i = 0; i < 4; ++i) cacc[nt][s][i] = 0.f;

#pragma unroll 1
        for (int c = 0; c < NCH; ++c) {
            uint32_t mb = smem_base + SM_MBAR + stg * 8;
            MBARRIER_WAIT_PARITY(mb, (phbits >> stg) & 1);
            phbits ^= (1u << stg);

            // read h_old for this block's columns from the staged copy
            if (c == mychunk) {
                const char* sb = (const char*)smem + SM_A + stg * CHKB;
                __nv_bfloat162 hh0 = *(const __nv_bfloat162*)(sb + ep0);
                __nv_bfloat162 hl0 = *(const __nv_bfloat162*)(sb + 16384 + ep0);
                __nv_bfloat162 hh1 = *(const __nv_bfloat162*)(sb + ep1);
                __nv_bfloat162 hl1 = *(const __nv_bfloat162*)(sb + 16384 + ep1);
                hold00 = __low2float(hh0) + __low2float(hl0);
                hold01 = __high2float(hh0) + __high2float(hl0);
                hold10 = __low2float(hh1) + __low2float(hl1);
                hold11 = __high2float(hh1) + __high2float(hl1);
            }

            uint32_t sbase = smem_base + SM_A + (uint32_t)(stg * CHKB) + arowb;
#pragma unroll
            for (int s2 = 0; s2 < 2; ++s2) {
                uint32_t bh[3][4], bl[3][4];
#pragma unroll
                for (int nt = 0; nt < 3; ++nt) {
                    uint32_t bb = smem_base + b_off[nt] + (uint32_t)(c * 128 + s2 * 64);
                    LDSM_X4(bh[nt][0], bh[nt][1], bh[nt][2], bh[nt][3], bb + SM_WHI);
                    LDSM_X4(bl[nt][0], bl[nt][1], bl[nt][2], bl[nt][3], bb + SM_WLO);
                }
                uint32_t ah[2][4], al[2][4];
#pragma unroll
                for (int s = 0; s < 2; ++s) {
                    int u = s2 * 4 + s * 2 + lhalf;
                    uint32_t aa = sbase + (uint32_t)(((u ^ ar7)) << 4);
                    LDSM_X4(ah[s][0], ah[s][1], ah[s][2], ah[s][3], aa);
                    LDSM_X4(al[s][0], al[s][1], al[s][2], al[s][3], aa + 16384);
                }
#pragma unroll
                for (int s = 0; s < 2; ++s)
#pragma unroll
                    for (int nt = 0; nt < 3; ++nt)
                        MMA16816(cacc[nt][s], ah[s], bh[nt][2 * s], bh[nt][2 * s + 1]);
#pragma unroll
                for (int s = 0; s < 2; ++s)
#pragma unroll
                    for (int nt = 0; nt < 3; ++nt)
                        MMA16816(cacc[nt][s], ah[s], bl[nt][2 * s], bl[nt][2 * s + 1]);
#pragma unroll
                for (int s = 0; s < 2; ++s)
#pragma unroll
                    for (int nt = 0; nt < 3; ++nt)
                        MMA16816(cacc[nt][s], al[s], bh[nt][2 * s], bh[nt][2 * s + 1]);
            }
            __syncthreads();

            if (c + NSTG < NCH && tid == 0) {
                while (ld_acq(&g_cnt[c + NSTG]) < tgt) { }
                MBAR_ARRIVE_EXPECT(mb, CHKB);
                BULK_G2S(smem_base + SM_A + (uint32_t)(stg * CHKB),
                         hsrc + (size_t)(c + NSTG) * CHKB, CHKB, mb);
            }
            stg = (stg + 1 == NSTG) ? 0 : stg + 1;
        }

        // merge k-parity accumulators
        float cfin[3][4];
#pragma unroll
        for (int nt = 0; nt < 3; ++nt)
#pragma unroll
            for (int i = 0; i < 4; ++i) cfin[nt][i] = cacc[nt][0][i] + cacc[nt][1][i];

        char* hcd = hdst + (size_t)mychunk * CHKB;
#pragma unroll
        for (int half = 0; half < 2; ++half) {
            int row = row0 + half * 8;
            int ib = 2 * half;
            float xr_ = half ? xr1.x : xr0.x, xr_1 = half ? xr1.y : xr0.y;
            float xz_ = half ? xz1.x : xz0.x, xz_1 = half ? xz1.y : xz0.y;
            float xn_ = half ? xn1.x : xn0.x, xn_1 = half ? xn1.y : xn0.y;
            float ho0 = half ? hold10 : hold00;
            float ho1 = half ? hold11 : hold01;

            float rg0 = sigm(xr_ + cfin[0][ib] + b_r0);
            float zg0 = sigm(xz_ + cfin[1][ib] + b_z0);
            float ng0 = tanh_fast(xn_ + rg0 * (cfin[2][ib] + b_n0));
            float o0 = gv * ((1.f - zg0) * ng0 + zg0 * ho0);

            float rg1 = sigm(xr_1 + cfin[0][ib + 1] + b_r1);
            float zg1 = sigm(xz_1 + cfin[1][ib + 1] + b_z1);
            float ng1 = tanh_fast(xn_1 + rg1 * (cfin[2][ib + 1] + b_n1));
            float o1 = gv1 * ((1.f - zg1) * ng1 + zg1 * ho1);

            if (t == TT - 1) {
                *(float2*)(out + (size_t)row * HH + j0 + jc) = make_float2(o0, o1);
            } else {
                __nv_bfloat16 h0 = __float2bfloat16_rn(o0);
                __nv_bfloat16 h1 = __float2bfloat16_rn(o1);
                __nv_bfloat162 hv; hv.x = h0; hv.y = h1;
                __nv_bfloat162 lv;
                lv.x = __float2bfloat16_rn(o0 - __bfloat162float(h0));
                lv.y = __float2bfloat16_rn(o1 - __bfloat162float(h1));
                uint32_t ep = half ? ep1 : ep0;
                *(__nv_bfloat162*)(hcd + ep) = hv;
                *(__nv_bfloat162*)(hcd + 16384 + ep) = lv;
            }
        }

        // signal production of this block's chunk for step t
        if (t < TT - 1) {
            __syncthreads();
            if (tid == 0) {
                __threadfence();
                atomicAdd(&g_cnt[mychunk], 1u);
            }
        }
    }
}

// ---------------- launch ---------------------------------------------------------
extern "C" void kernel_launch(void* const* d_in, const int* in_sizes, int n_in,
                              void* d_out, int out_size) {
    const int* x        = (const int*)d_in[0];
    const int* key_ids  = (const int*)d_in[1];
    const float* emb    = (const float*)d_in[2];
    const float* W_ih   = (const float*)d_in[3];
    const float* W_hh   = (const float*)d_in[4];
    const float* b_ih   = (const float*)d_in[5];
    const float* b_hh   = (const float*)d_in[6];
    const float* W_g    = (const float*)d_in[7];
    const float* b_g    = (const float*)d_in[8];
    float* out = (float*)d_out;

    cudaFuncSetAttribute(recur_kernel, cudaFuncAttributeMaxDynamicSharedMemorySize, SM_TOTAL);
    cudaFuncSetAttribute(keyall_kernel, cudaFuncAttributeMaxDynamicSharedMemorySize, KA_TOTAL);

    // harness offset is 2 -> ncu (-s 5) profiles our launch index 3 = recur_kernel
    zero_kernel<<<(BB * HH + 255) / 256, 256>>>();                               // 0
    keyall_kernel<<<NBLK, 256, KA_TOTAL>>>(key_ids, emb, W_ih, W_hh,
                                           b_ih, b_hh, W_g, b_g);                // 1
    dim3 xg(H3 / XBN, (BB * TT) / XBM);
    xproj_kernel<<<xg, 256>>>(x, emb, W_ih, b_ih);                               // 2
    recur_kernel<<<NBLK, RTH, SM_TOTAL>>>(W_hh, b_hh, out);                      // 3
    pad_kernel<<<1, 32>>>();                                                     // 4
    pad_kernel<<<1, 32>>>();                                                     // 5
}

// round 16
// speedup vs baseline: 1.4157x; 1.3766x over previous
#include <cuda_runtime.h>
#include <cuda_fp16.h>
#include <math.h>
#include <stdint.h>

#define BB 128
#define TT 512
#define EE 300
#define HH 1024
#define H3 3072
#define KEYLEN 15

#define NBLK 128          // persistent blocks (1 per SM)
#define RTH  256          // recurrence threads (8 warps)
#define CHK  64           // K elements per chunk
#define NCH  (HH / CHK)   // 16 chunks per step
#define CHKB 32768        // bytes per packed chunk (hi 16KB + lo 16KB)
#define NSTG 3            // pipeline stages

// recur SMEM layout (dynamic, bytes)
#define SM_WF    0                       // 24 x 1032 fp16 = 49536
#define SM_A     50176                   // 1024-aligned; 3 stages x 32768
#define SM_BIAS  148480                  // 24 floats
#define SM_GATE  148576                  // 8 floats
#define SM_MBAR  148608                  // 3 mbarriers (u64)
#define SM_TOTAL 148736

// keyall SMEM layout (dynamic, bytes)
#define KA_KE    0
#define KA_WSL   18048
#define KA_KXP   116352
#define KA_KH    117792
#define KA_HP    121888
#define KA_TOTAL 122112

typedef unsigned long long ull;

// ---------------- device scratch (static; no cudaMalloc) ------------------------
__device__ float g_xproj[(size_t)BB * TT * H3];        // [t][b][3H]
// hidden state, chunk-packed fp16 + pre-swizzled: [sel][chunk][hi/lo][row][64]
__device__ __align__(1024) __half g_hpk[2][NCH][2][BB][CHK];
__device__ float g_kh[HH];
__device__ float g_gate[HH];
__device__ volatile unsigned g_flags[NBLK];
__device__ volatile unsigned g_kflags[NBLK];

__device__ __forceinline__ float sigm(float v) {
    return __fdividef(1.f, 1.f + __expf(-v));
}
__device__ __forceinline__ float tanh_fast(float x) {
    float e = __expf(2.f * x);
    return 1.f - __fdividef(2.f, e + 1.f);
}

__device__ __forceinline__ void ffma2(ull& d, ull a, ull b) {
    asm("fma.rn.f32x2 %0, %1, %2, %0;" : "+l"(d) : "l"(a), "l"(b));
}
__device__ __forceinline__ float hsum2(ull v) {
    return __int_as_float((unsigned)(v & 0xffffffffull)) + __int_as_float((unsigned)(v >> 32));
}
__device__ __forceinline__ uint32_t smem_to_u32(const void* p) {
    uint32_t a;
    asm("{ .reg .u64 t; cvta.to.shared.u64 t, %1; cvt.u32.u64 %0, t; }" : "=r"(a) : "l"(p));
    return a;
}

#define LDSM_X4(r0, r1, r2, r3, addr) \
    asm volatile("ldmatrix.sync.aligned.m8n8.x4.shared.b16 {%0,%1,%2,%3}, [%4];" \
                 : "=r"(r0), "=r"(r1), "=r"(r2), "=r"(r3) : "r"(addr))

// fp16 MMA, fp32 accumulate; no volatile (pure register op)
#define MMA16816(c, a, b0, b1) \
    asm("mma.sync.aligned.m16n8k16.row.col.f32.f16.f16.f32 " \
        "{%0,%1,%2,%3},{%4,%5,%6,%7},{%8,%9},{%0,%1,%2,%3};" \
        : "+f"((c)[0]), "+f"((c)[1]), "+f"((c)[2]), "+f"((c)[3]) \
        : "r"((a)[0]), "r"((a)[1]), "r"((a)[2]), "r"((a)[3]), "r"(b0), "r"(b1))

#define MBARRIER_INIT(mb, c) \
    asm volatile("mbarrier.init.shared.b64 [%0], %1;" :: "r"((uint32_t)(mb)), "r"((uint32_t)(c)) : "memory")
#define MBAR_ARRIVE_EXPECT(mb, bytes) \
    asm volatile("mbarrier.arrive.expect_tx.shared.b64 _, [%0], %1;" \
                 :: "r"((uint32_t)(mb)), "r"((uint32_t)(bytes)) : "memory")
#define BULK_G2S(dst, src, bytes, mb) \
    asm volatile("cp.async.bulk.shared::cta.global.mbarrier::complete_tx::bytes [%0], [%1], %2, [%3];" \
                 :: "r"((uint32_t)(dst)), "l"(src), "r"((uint32_t)(bytes)), "r"((uint32_t)(mb)) : "memory")
#define MBARRIER_WAIT_PARITY(mb, ph) do { \
    uint32_t _m = (uint32_t)(mb); uint32_t _p = (uint32_t)(ph); uint32_t _d; \
    asm volatile("{\n\t.reg .pred p;\n\t" \
        "mbarrier.try_wait.parity.acquire.cta.shared::cta.b64 p, [%1], %2;\n\t" \
        "selp.b32 %0, 1, 0, p;\n\t}" : "=r"(_d) : "r"(_m), "r"(_p) : "memory"); \
    if (!_d) { \
        asm volatile("{\n\t.reg .pred P1;\n\t" \
            "WL_%=:\n\t" \
            "mbarrier.try_wait.parity.acquire.cta.shared::cta.b64 P1, [%0], %1, 0x989680;\n\t" \
            "@P1 bra.uni WD_%=;\n\tbra.uni WL_%=;\n\tWD_%=:\n\t}" \
            :: "r"(_m), "r"(_p) : "memory"); \
    } } while (0)

// ---------------- init ----------------------------------------------------------
__global__ void zero_kernel() {
    int i = blockIdx.x * blockDim.x + threadIdx.x;
    if (i < (NCH * 2 * BB * CHK) / 2) ((uint32_t*)g_hpk)[i] = 0u;  // zero sel 0
    if (i < HH) g_kh[i] = 0.f;
    if (i < NBLK) { g_flags[i] = 0u; g_kflags[i] = 0u; }
}

__global__ void pad_kernel() {}

// ---------------- xproj (f32x2 scalar GEMM) --------------------------------------
#define XBM 128
#define XBN 64
#define XBK 20
__global__ void xproj_kernel(const int* __restrict__ x, const float* __restrict__ emb,
                             const float* __restrict__ Wih, const float* __restrict__ bih) {
    __shared__ float As[XBM * XBK];
    __shared__ float Bs[XBN * XBK];
    __shared__ int rid[XBM];

    int tid = threadIdx.x;
    int i0 = blockIdx.y * XBM;
    int g0 = blockIdx.x * XBN;

    if (tid < XBM) {
        int i = i0 + tid;
        int t = i / BB, b = i % BB;
        rid[tid] = x[b * TT + t];
    }
    __syncthreads();

    int tx = tid & 15;
    int ty = tid >> 4;

    ull acc[8][4];
#pragma unroll
    for (int r = 0; r < 8; ++r)
#pragma unroll
        for (int c = 0; c < 4; ++c) acc[r][c] = 0ull;

    for (int k0 = 0; k0 < EE; k0 += XBK) {
        for (int idx = tid; idx < XBM * XBK; idx += 256) {
            int row = idx / XBK, kk = idx % XBK;
            As[row * XBK + kk] = emb[(size_t)rid[row] * EE + k0 + kk];
        }
        for (int idx = tid; idx < XBN * XBK; idx += 256) {
            int c = idx / XBK, kk = idx % XBK;
            Bs[c * XBK + kk] = Wih[(size_t)(g0 + c) * EE + k0 + kk];
        }
        __syncthreads();
#pragma unroll
        for (int kp = 0; kp < XBK / 2; ++kp) {
            ull bv[4];
#pragma unroll
            for (int c = 0; c < 4; ++c)
                bv[c] = *(const ull*)(Bs + (tx * 4 + c) * XBK + 2 * kp);
#pragma unroll
            for (int r = 0; r < 8; ++r) {
                ull av = *(const ull*)(As + (ty * 8 + r) * XBK + 2 * kp);
#pragma unroll
                for (int c = 0; c < 4; ++c) ffma2(acc[r][c], av, bv[c]);
            }
        }
        __syncthreads();
    }
#pragma unroll
    for (int r = 0; r < 8; ++r) {
        size_t i = (size_t)(i0 + ty * 8 + r);
#pragma unroll
        for (int c = 0; c < 4; ++c) {
            int g = g0 + tx * 4 + c;
            g_xproj[i * H3 + g] = hsum2(acc[r][c]) + bih[g];
        }
    }
}

// ---------------- barriers -------------------------------------------------------
__device__ __forceinline__ void grid_barrier(unsigned target) {
    __syncthreads();
    if (threadIdx.x == 0) {
        __threadfence();
        g_flags[blockIdx.x] = target;
    }
    if (threadIdx.x < NBLK) {
        while (g_flags[threadIdx.x] < target) { }
    }
    __syncthreads();
}
__device__ __forceinline__ void kgrid_barrier(unsigned target) {
    __syncthreads();
    if (threadIdx.x == 0) {
        __threadfence();
        g_kflags[blockIdx.x] = target;
    }
    if (threadIdx.x < NBLK) {
        while (g_kflags[threadIdx.x] < target) { }
    }
    __syncthreads();
}

// ---------------- fused key-GRU kernel -------------------------------------------
__global__ void __launch_bounds__(256, 1)
keyall_kernel(const int* __restrict__ key_ids, const float* __restrict__ emb,
              const float* __restrict__ Wih, const float* __restrict__ Whh,
              const float* __restrict__ bih, const float* __restrict__ bhh,
              const float* __restrict__ Wg, const float* __restrict__ bg) {
    extern __shared__ char smem[];
    float* ke    = (float*)(smem + KA_KE);
    float* Wsl   = (float*)(smem + KA_WSL);
    float* kxp_s = (float*)(smem + KA_KXP);
    float* kh_s  = (float*)(smem + KA_KH);
    float* hp_s  = (float*)(smem + KA_HP);

    int tid = threadIdx.x;
    int lane = tid & 31, w = tid >> 5;
    int j0 = blockIdx.x * 8;

    for (int i = tid; i < KEYLEN * EE; i += 256) {
        int t = i / EE, e = i % EE;
        ke[i] = emb[(size_t)key_ids[t] * EE + e];
    }
    for (int i = tid; i < 24 * HH; i += 256) {
        int n = i >> 10, k = i & 1023;
        Wsl[i] = Whh[(size_t)((n >> 3) * HH + j0 + (n & 7)) * HH + k];
    }
    __syncthreads();

    for (int i = tid; i < KEYLEN * 24; i += 256) {
        int t = i / 24, n = i % 24;
        int grow = (n >> 3) * HH + j0 + (n & 7);
        const float* wr = Wih + (size_t)grow * EE;
        float acc = 0.f;
        for (int e = 0; e < EE; ++e) acc += wr[e] * ke[t * EE + e];
        kxp_s[i] = acc + bih[grow];
    }
    __syncthreads();

    for (int t = 0; t < KEYLEN; ++t) {
        for (int i = tid; i < HH; i += 256) kh_s[i] = __ldcg(&g_kh[i]);
        __syncthreads();
#pragma unroll
        for (int rr = 0; rr < 3; ++rr) {
            int n = w * 3 + rr;
            const float* wr = Wsl + n * HH;
            float a = 0.f;
            for (int k = lane; k < HH; k += 32) a += wr[k] * kh_s[k];
#pragma unroll
            for (int o = 16; o; o >>= 1) a += __shfl_xor_sync(0xffffffffu, a, o);
            if (lane == 0) hp_s[n] = a;
        }
        __syncthreads();
        if (tid < 8) {
            int j = j0 + tid;
            float r = sigm(kxp_s[t * 24 + tid] + hp_s[tid] + bhh[j]);
            float z = sigm(kxp_s[t * 24 + 8 + tid] + hp_s[8 + tid] + bhh[HH + j]);
            float n2 = tanh_fast(kxp_s[t * 24 + 16 + tid] + r * (hp_s[16 + tid] + bhh[2 * HH + j]));
            g_kh[j] = (1.f - z) * n2 + z * kh_s[j];
        }
        kgrid_barrier((unsigned)(t + 1));
    }

    for (int i = tid; i < HH; i += 256) kh_s[i] = __ldcg(&g_kh[i]);
    __syncthreads();
    {
        int j = j0 + w;
        const float* wr = Wg + (size_t)j * HH;
        float a = 0.f;
        for (int k = lane; k < HH; k += 32) a += wr[k] * kh_s[k];
#pragma unroll
        for (int o = 16; o; o >>= 1) a += __shfl_xor_sync(0xffffffffu, a, o);
        if (lane == 0) g_gate[j] = sigm(a + bg[j]);
    }
}

// ---------------- persistent HMMA recurrence (fp16 2-pass, R13 skeleton) ---------
// 128 blocks x 256 threads. W_hh slice in SMEM as SINGLE fp16. Hidden state
// chunk-packed fp16 hi/lo (16 chunks of K=64), 3-stage 32KB bulk-copy pipeline,
// rigid grid barrier. Per k32 block: 3 B-LDSM + 4 A-LDSM, 12 MMAs (hi*W + lo*W).
__global__ void __launch_bounds__(RTH, 1)
recur_kernel(const float* __restrict__ Whh, const float* __restrict__ bhh,
             float* __restrict__ out) {
    extern __shared__ char smem[];
    uint32_t smem_base = smem_to_u32(smem);
    float* bias_s = (float*)(smem + SM_BIAS);
    float* gate_s = (float*)(smem + SM_GATE);
    __half* wf_s = (__half*)(smem + SM_WF);

    int tid = threadIdx.x;
    int lane = tid & 31;
    int w = tid >> 5;
    int j0 = blockIdx.x * 8;

    if (tid == 0) {
#pragma unroll
        for (int s = 0; s < NSTG; ++s) MBARRIER_INIT(smem_base + SM_MBAR + s * 8, 1);
    }
    asm volatile("fence.proxy.async.shared::cta;" ::: "memory");

    // W_hh slice: rows n = gate*8 + cj, k-contiguous fp16, row stride 1032
    for (int idx = tid; idx < 24 * HH; idx += RTH) {
        int n = idx >> 10, k = idx & (HH - 1);
        float f = Whh[(size_t)((n >> 3) * HH + j0 + (n & 7)) * HH + k];
        wf_s[n * 1032 + k] = __float2half_rn(f);
    }
    if (tid < 24) bias_s[tid] = bhh[(tid >> 3) * HH + j0 + (tid & 7)];
    if (tid < 8)  gate_s[tid] = g_gate[j0 + tid];
    __syncthreads();

    // fragment geometry (identical to R13)
    int arow = 16 * w + (lane & 15);
    int ar7 = arow & 7;
    uint32_t arowb = (uint32_t)(arow * 128);
    int lhalf = lane >> 4;
    uint32_t b_off[3];
#pragma unroll
    for (int nt = 0; nt < 3; ++nt)
        b_off[nt] = (uint32_t)((nt * 8 + (lane & 7)) * 2064 + (lane >> 3) * 16);

    int row0 = 16 * w + (lane >> 2);
    int jc = 2 * (lane & 3);
    float gv = gate_s[jc], gv1 = gate_s[jc + 1];
    float b_r0 = bias_s[jc],      b_r1 = bias_s[jc + 1];
    float b_z0 = bias_s[8 + jc],  b_z1 = bias_s[8 + jc + 1];
    float b_n0 = bias_s[16 + jc], b_n1 = bias_s[16 + jc + 1];

    int mychunk = j0 >> 6;
    int cw = (j0 & 63) + jc;
    uint32_t ep0 = (uint32_t)(((row0 * 128 + cw * 2) ^ ((row0 & 7) << 4)));
    uint32_t ep1 = (uint32_t)((((row0 + 8) * 128 + cw * 2) ^ (((row0 + 8) & 7) << 4)));

    unsigned phbits = 0;
    int stg = 0;

#pragma unroll 1
    for (int t = 0; t < TT; ++t) {
        int sel = t & 1;
        const char* hsrc = (const char*)&g_hpk[sel][0][0][0][0];
        char* hdst = (char*)&g_hpk[sel ^ 1][0][0][0][0];
        const float* xp = g_xproj + (size_t)t * BB * H3;

        if (tid == 0) {
            int s = stg;
#pragma unroll
            for (int p = 0; p < NSTG; ++p) {
                uint32_t mb = smem_base + SM_MBAR + s * 8;
                MBAR_ARRIVE_EXPECT(mb, CHKB);
                BULK_G2S(smem_base + SM_A + s * CHKB, hsrc + (size_t)p * CHKB, CHKB, mb);
                s = (s + 1 == NSTG) ? 0 : s + 1;
            }
        }

        const float* xpr0 = xp + (size_t)row0 * H3 + j0 + jc;
        const float* xpr1 = xp + (size_t)(row0 + 8) * H3 + j0 + jc;
        float2 xr0 = __ldcs((const float2*)(xpr0));
        float2 xz0 = __ldcs((const float2*)(xpr0 + HH));
        float2 xn0 = __ldcs((const float2*)(xpr0 + 2 * HH));
        float2 xr1 = __ldcs((const float2*)(xpr1));
        float2 xz1 = __ldcs((const float2*)(xpr1 + HH));
        float2 xn1 = __ldcs((const float2*)(xpr1 + 2 * HH));
        const char* hcs = hsrc + (size_t)mychunk * CHKB;
        __half2 hh0 = *(const __half2*)(hcs + ep0);
        __half2 hl0 = *(const __half2*)(hcs + 16384 + ep0);
        __half2 hh1 = *(const __half2*)(hcs + ep1);
        __half2 hl1 = *(const __half2*)(hcs + 16384 + ep1);
        float hold00 = __low2float(hh0) + __low2float(hl0);
        float hold01 = __high2float(hh0) + __high2float(hl0);
        float hold10 = __low2float(hh1) + __low2float(hl1);
        float hold11 = __high2float(hh1) + __high2float(hl1);

        float cacc[3][2][4];
#pragma unroll
        for (int nt = 0; nt < 3; ++nt)
#pragma unroll
            for (int s = 0; s < 2; ++s)
#pragma unroll
                for (int i = 0; i < 4; ++i) cacc[nt][s][i] = 0.f;

#pragma unroll 1
        for (int c = 0; c < NCH; ++c) {
            uint32_t mb = smem_base + SM_MBAR + stg * 8;
            MBARRIER_WAIT_PARITY(mb, (phbits >> stg) & 1);
            phbits ^= (1u << stg);

            uint32_t sbase = smem_base + SM_A + (uint32_t)(stg * CHKB) + arowb;
#pragma unroll
            for (int s2 = 0; s2 < 2; ++s2) {
                // B fragments: single fp16 W, 3 n-tiles (k32)
                uint32_t bf[3][4];
#pragma unroll
                for (int nt = 0; nt < 3; ++nt) {
                    uint32_t bb = smem_base + b_off[nt] + (uint32_t)(c * 128 + s2 * 64);
                    LDSM_X4(bf[nt][0], bf[nt][1], bf[nt][2], bf[nt][3], bb + SM_WF);
                }
                // A fragments: hi and lo arrays, both k-steps
                uint32_t ah[2][4], al[2][4];
#pragma unroll
                for (int s = 0; s < 2; ++s) {
                    int u = s2 * 4 + s * 2 + lhalf;
                    uint32_t aa = sbase + (uint32_t)(((u ^ ar7)) << 4);
                    LDSM_X4(ah[s][0], ah[s][1], ah[s][2], ah[s][3], aa);
                    LDSM_X4(al[s][0], al[s][1], al[s][2], al[s][3], aa + 16384);
                }
                // 12 MMAs, same-accumulator distance = 6
#pragma unroll
                for (int s = 0; s < 2; ++s)
#pragma unroll
                    for (int nt = 0; nt < 3; ++nt)
                        MMA16816(cacc[nt][s], ah[s], bf[nt][2 * s], bf[nt][2 * s + 1]);
#pragma unroll
                for (int s = 0; s < 2; ++s)
#pragma unroll
                    for (int nt = 0; nt < 3; ++nt)
                        MMA16816(cacc[nt][s], al[s], bf[nt][2 * s], bf[nt][2 * s + 1]);
            }
            __syncthreads();

            if (c + NSTG < NCH && tid == 0) {
                MBAR_ARRIVE_EXPECT(mb, CHKB);
                BULK_G2S(smem_base + SM_A + (uint32_t)(stg * CHKB),
                         hsrc + (size_t)(c + NSTG) * CHKB, CHKB, mb);
            }
            stg = (stg + 1 == NSTG) ? 0 : stg + 1;
        }

        float cfin[3][4];
#pragma unroll
        for (int nt = 0; nt < 3; ++nt)
#pragma unroll
            for (int i = 0; i < 4; ++i) cfin[nt][i] = cacc[nt][0][i] + cacc[nt][1][i];

        char* hcd = hdst + (size_t)mychunk * CHKB;
#pragma unroll
        for (int half = 0; half < 2; ++half) {
            int row = row0 + half * 8;
            int ib = 2 * half;
            float xr_ = half ? xr1.x : xr0.x, xr_1 = half ? xr1.y : xr0.y;
            float xz_ = half ? xz1.x : xz0.x, xz_1 = half ? xz1.y : xz0.y;
            float xn_ = half ? xn1.x : xn0.x, xn_1 = half ? xn1.y : xn0.y;
            float ho0 = half ? hold10 : hold00;
            float ho1 = half ? hold11 : hold01;

            float rg0 = sigm(xr_ + cfin[0][ib] + b_r0);
            float zg0 = sigm(xz_ + cfin[1][ib] + b_z0);
            float ng0 = tanh_fast(xn_ + rg0 * (cfin[2][ib] + b_n0));
            float o0 = gv * ((1.f - zg0) * ng0 + zg0 * ho0);

            float rg1 = sigm(xr_1 + cfin[0][ib + 1] + b_r1);
            float zg1 = sigm(xz_1 + cfin[1][ib + 1] + b_z1);
            float ng1 = tanh_fast(xn_1 + rg1 * (cfin[2][ib + 1] + b_n1));
            float o1 = gv1 * ((1.f - zg1) * ng1 + zg1 * ho1);

            if (t == TT - 1) {
                *(float2*)(out + (size_t)row * HH + j0 + jc) = make_float2(o0, o1);
            } else {
                __half h0 = __float2half_rn(o0);
                __half h1 = __float2half_rn(o1);
                __half2 hv; hv.x = h0; hv.y = h1;
                __half2 lv;
                lv.x = __float2half_rn(o0 - __half2float(h0));
                lv.y = __float2half_rn(o1 - __half2float(h1));
                uint32_t ep = half ? ep1 : ep0;
                *(__half2*)(hcd + ep) = hv;
                *(__half2*)(hcd + 16384 + ep) = lv;
            }
        }

        if (t < TT - 1) grid_barrier((unsigned)(t + 1));
    }
}

// ---------------- launch ---------------------------------------------------------
extern "C" void kernel_launch(void* const* d_in, const int* in_sizes, int n_in,
                              void* d_out, int out_size) {
    const int* x        = (const int*)d_in[0];
    const int* key_ids  = (const int*)d_in[1];
    const float* emb    = (const float*)d_in[2];
    const float* W_ih   = (const float*)d_in[3];
    const float* W_hh   = (const float*)d_in[4];
    const float* b_ih   = (const float*)d_in[5];
    const float* b_hh   = (const float*)d_in[6];
    const float* W_g    = (const float*)d_in[7];
    const float* b_g    = (const float*)d_in[8];
    float* out = (float*)d_out;

    cudaFuncSetAttribute(recur_kernel, cudaFuncAttributeMaxDynamicSharedMemorySize, SM_TOTAL);
    cudaFuncSetAttribute(keyall_kernel, cudaFuncAttributeMaxDynamicSharedMemorySize, KA_TOTAL);

    // recur stays at launch index 3 (ncu -s 5 with harness offset 2 profiles it)
    zero_kernel<<<(BB * HH + 255) / 256, 256>>>();                               // 0
    keyall_kernel<<<NBLK, 256, KA_TOTAL>>>(key_ids, emb, W_ih, W_hh,
                                           b_ih, b_hh, W_g, b_g);                // 1
    dim3 xg(H3 / XBN, (BB * TT) / XBM);
    xproj_kernel<<<xg, 256>>>(x, emb, W_ih, b_ih);                               // 2
    recur_kernel<<<NBLK, RTH, SM_TOTAL>>>(W_hh, b_hh, out);                      // 3
    pad_kernel<<<1, 32>>>();                                                     // 4
    pad_kernel<<<1, 32>>>();                                                     // 5
}

// round 17
// speedup vs baseline: 1.4814x; 1.0464x over previous
#include <cuda_runtime.h>
#include <cuda_fp16.h>
#include <math.h>
#include <stdint.h>

#define BB 128
#define TT 512
#define EE 300
#define HH 1024
#define H3 3072
#define KEYLEN 15

#define NBLK 128          // persistent blocks (1 per SM)
#define RTH  512          // recurrence threads (16 warps, 2 groups of 8)
#define CHK  64           // K elements per chunk
#define NCH  (HH / CHK)   // 16 chunks per step (8 per group)
#define CHKB 32768        // bytes per packed chunk (hi 16KB + lo 16KB)

// recur SMEM layout (dynamic, bytes)
#define SM_WF    0                       // 24 x 1032 fp16 = 49536
#define SM_A     50176                   // 1024-aligned; 4 stage buffers x 32768
#define SM_PART  181248                  // 256 x 13 floats = 13312 (padded partials)
#define SM_BIAS  194560                  // 24 floats
#define SM_GATE  194656                  // 8 floats
#define SM_MBAR  194688                  // 4 mbarriers (u64)
#define SM_TOTAL 194816

// keyall SMEM layout (dynamic, bytes)
#define KA_KE    0
#define KA_WSL   18048
#define KA_KXP   116352
#define KA_KH    117792
#define KA_HP    121888
#define KA_TOTAL 122112

typedef unsigned long long ull;

// ---------------- device scratch (static; no cudaMalloc) ------------------------
__device__ float g_xproj[(size_t)BB * TT * H3];        // [t][b][3H]
// hidden state, chunk-packed fp16 + pre-swizzled: [sel][chunk][hi/lo][row][64]
__device__ __align__(1024) __half g_hpk[2][NCH][2][BB][CHK];
__device__ float g_kh[HH];
__device__ float g_gate[HH];
__device__ volatile unsigned g_flags[NBLK];
__device__ volatile unsigned g_kflags[NBLK];

__device__ __forceinline__ float sigm(float v) {
    return __fdividef(1.f, 1.f + __expf(-v));
}
__device__ __forceinline__ float tanh_fast(float x) {
    float e = __expf(2.f * x);
    return 1.f - __fdividef(2.f, e + 1.f);
}

__device__ __forceinline__ void ffma2(ull& d, ull a, ull b) {
    asm("fma.rn.f32x2 %0, %1, %2, %0;" : "+l"(d) : "l"(a), "l"(b));
}
__device__ __forceinline__ float hsum2(ull v) {
    return __int_as_float((unsigned)(v & 0xffffffffull)) + __int_as_float((unsigned)(v >> 32));
}
__device__ __forceinline__ uint32_t smem_to_u32(const void* p) {
    uint32_t a;
    asm("{ .reg .u64 t; cvta.to.shared.u64 t, %1; cvt.u32.u64 %0, t; }" : "=r"(a) : "l"(p));
    return a;
}

#define LDSM_X4(r0, r1, r2, r3, addr) \
    asm volatile("ldmatrix.sync.aligned.m8n8.x4.shared.b16 {%0,%1,%2,%3}, [%4];" \
                 : "=r"(r0), "=r"(r1), "=r"(r2), "=r"(r3) : "r"(addr))

// fp16 MMA, fp32 accumulate; no volatile (pure register op)
#define MMA16816(c, a, b0, b1) \
    asm("mma.sync.aligned.m16n8k16.row.col.f32.f16.f16.f32 " \
        "{%0,%1,%2,%3},{%4,%5,%6,%7},{%8,%9},{%0,%1,%2,%3};" \
        : "+f"((c)[0]), "+f"((c)[1]), "+f"((c)[2]), "+f"((c)[3]) \
        : "r"((a)[0]), "r"((a)[1]), "r"((a)[2]), "r"((a)[3]), "r"(b0), "r"(b1))

#define NAMED_BAR(id, cnt) \
    asm volatile("bar.sync %0, %1;" :: "r"(id), "r"(cnt) : "memory")

#define MBARRIER_INIT(mb, c) \
    asm volatile("mbarrier.init.shared.b64 [%0], %1;" :: "r"((uint32_t)(mb)), "r"((uint32_t)(c)) : "memory")
#define MBAR_ARRIVE_EXPECT(mb, bytes) \
    asm volatile("mbarrier.arrive.expect_tx.shared.b64 _, [%0], %1;" \
                 :: "r"((uint32_t)(mb)), "r"((uint32_t)(bytes)) : "memory")
#define BULK_G2S(dst, src, bytes, mb) \
    asm volatile("cp.async.bulk.shared::cta.global.mbarrier::complete_tx::bytes [%0], [%1], %2, [%3];" \
                 :: "r"((uint32_t)(dst)), "l"(src), "r"((uint32_t)(bytes)), "r"((uint32_t)(mb)) : "memory")
#define MBARRIER_WAIT_PARITY(mb, ph) do { \
    uint32_t _m = (uint32_t)(mb); uint32_t _p = (uint32_t)(ph); uint32_t _d; \
    asm volatile("{\n\t.reg .pred p;\n\t" \
        "mbarrier.try_wait.parity.acquire.cta.shared::cta.b64 p, [%1], %2;\n\t" \
        "selp.b32 %0, 1, 0, p;\n\t}" : "=r"(_d) : "r"(_m), "r"(_p) : "memory"); \
    if (!_d) { \
        asm volatile("{\n\t.reg .pred P1;\n\t" \
            "WL_%=:\n\t" \
            "mbarrier.try_wait.parity.acquire.cta.shared::cta.b64 P1, [%0], %1, 0x989680;\n\t" \
            "@P1 bra.uni WD_%=;\n\tbra.uni WL_%=;\n\tWD_%=:\n\t}" \
            :: "r"(_m), "r"(_p) : "memory"); \
    } } while (0)

// ---------------- init ----------------------------------------------------------
__global__ void zero_kernel() {
    int i = blockIdx.x * blockDim.x + threadIdx.x;
    if (i < (NCH * 2 * BB * CHK) / 2) ((uint32_t*)g_hpk)[i] = 0u;  // zero sel 0
    if (i < HH) g_kh[i] = 0.f;
    if (i < NBLK) { g_flags[i] = 0u; g_kflags[i] = 0u; }
}

__global__ void pad_kernel() {}

// ---------------- xproj (f32x2 scalar GEMM) --------------------------------------
#define XBM 128
#define XBN 64
#define XBK 20
__global__ void xproj_kernel(const int* __restrict__ x, const float* __restrict__ emb,
                             const float* __restrict__ Wih, const float* __restrict__ bih) {
    __shared__ float As[XBM * XBK];
    __shared__ float Bs[XBN * XBK];
    __shared__ int rid[XBM];

    int tid = threadIdx.x;
    int i0 = blockIdx.y * XBM;
    int g0 = blockIdx.x * XBN;

    if (tid < XBM) {
        int i = i0 + tid;
        int t = i / BB, b = i % BB;
        rid[tid] = x[b * TT + t];
    }
    __syncthreads();

    int tx = tid & 15;
    int ty = tid >> 4;

    ull acc[8][4];
#pragma unroll
    for (int r = 0; r < 8; ++r)
#pragma unroll
        for (int c = 0; c < 4; ++c) acc[r][c] = 0ull;

    for (int k0 = 0; k0 < EE; k0 += XBK) {
        for (int idx = tid; idx < XBM * XBK; idx += 256) {
            int row = idx / XBK, kk = idx % XBK;
            As[row * XBK + kk] = emb[(size_t)rid[row] * EE + k0 + kk];
        }
        for (int idx = tid; idx < XBN * XBK; idx += 256) {
            int c = idx / XBK, kk = idx % XBK;
            Bs[c * XBK + kk] = Wih[(size_t)(g0 + c) * EE + k0 + kk];
        }
        __syncthreads();
#pragma unroll
        for (int kp = 0; kp < XBK / 2; ++kp) {
            ull bv[4];
#pragma unroll
            for (int c = 0; c < 4; ++c)
                bv[c] = *(const ull*)(Bs + (tx * 4 + c) * XBK + 2 * kp);
#pragma unroll
            for (int r = 0; r < 8; ++r) {
                ull av = *(const ull*)(As + (ty * 8 + r) * XBK + 2 * kp);
#pragma unroll
                for (int c = 0; c < 4; ++c) ffma2(acc[r][c], av, bv[c]);
            }
        }
        __syncthreads();
    }
#pragma unroll
    for (int r = 0; r < 8; ++r) {
        size_t i = (size_t)(i0 + ty * 8 + r);
#pragma unroll
        for (int c = 0; c < 4; ++c) {
            int g = g0 + tx * 4 + c;
            g_xproj[i * H3 + g] = hsum2(acc[r][c]) + bih[g];
        }
    }
}

// ---------------- barriers -------------------------------------------------------
__device__ __forceinline__ void grid_barrier(unsigned target) {
    __syncthreads();
    if (threadIdx.x == 0) {
        __threadfence();
        g_flags[blockIdx.x] = target;
    }
    if (threadIdx.x < NBLK) {
        while (g_flags[threadIdx.x] < target) { }
    }
    __syncthreads();
}
__device__ __forceinline__ void kgrid_barrier(unsigned target) {
    __syncthreads();
    if (threadIdx.x == 0) {
        __threadfence();
        g_kflags[blockIdx.x] = target;
    }
    if (threadIdx.x < NBLK) {
        while (g_kflags[threadIdx.x] < target) { }
    }
    __syncthreads();
}

// ---------------- fused key-GRU kernel -------------------------------------------
__global__ void __launch_bounds__(256, 1)
keyall_kernel(const int* __restrict__ key_ids, const float* __restrict__ emb,
              const float* __restrict__ Wih, const float* __restrict__ Whh,
              const float* __restrict__ bih, const float* __restrict__ bhh,
              const float* __restrict__ Wg, const float* __restrict__ bg) {
    extern __shared__ char smem[];
    float* ke    = (float*)(smem + KA_KE);
    float* Wsl   = (float*)(smem + KA_WSL);
    float* kxp_s = (float*)(smem + KA_KXP);
    float* kh_s  = (float*)(smem + KA_KH);
    float* hp_s  = (float*)(smem + KA_HP);

    int tid = threadIdx.x;
    int lane = tid & 31, w = tid >> 5;
    int j0 = blockIdx.x * 8;

    for (int i = tid; i < KEYLEN * EE; i += 256) {
        int t = i / EE, e = i % EE;
        ke[i] = emb[(size_t)key_ids[t] * EE + e];
    }
    for (int i = tid; i < 24 * HH; i += 256) {
        int n = i >> 10, k = i & 1023;
        Wsl[i] = Whh[(size_t)((n >> 3) * HH + j0 + (n & 7)) * HH + k];
    }
    __syncthreads();

    for (int i = tid; i < KEYLEN * 24; i += 256) {
        int t = i / 24, n = i % 24;
        int grow = (n >> 3) * HH + j0 + (n & 7);
        const float* wr = Wih + (size_t)grow * EE;
        float acc = 0.f;
        for (int e = 0; e < EE; ++e) acc += wr[e] * ke[t * EE + e];
        kxp_s[i] = acc + bih[grow];
    }
    __syncthreads();

    for (int t = 0; t < KEYLEN; ++t) {
        for (int i = tid; i < HH; i += 256) kh_s[i] = __ldcg(&g_kh[i]);
        __syncthreads();
#pragma unroll
        for (int rr = 0; rr < 3; ++rr) {
            int n = w * 3 + rr;
            const float* wr = Wsl + n * HH;
            float a = 0.f;
            for (int k = lane; k < HH; k += 32) a += wr[k] * kh_s[k];
#pragma unroll
            for (int o = 16; o; o >>= 1) a += __shfl_xor_sync(0xffffffffu, a, o);
            if (lane == 0) hp_s[n] = a;
        }
        __syncthreads();
        if (tid < 8) {
            int j = j0 + tid;
            float r = sigm(kxp_s[t * 24 + tid] + hp_s[tid] + bhh[j]);
            float z = sigm(kxp_s[t * 24 + 8 + tid] + hp_s[8 + tid] + bhh[HH + j]);
            float n2 = tanh_fast(kxp_s[t * 24 + 16 + tid] + r * (hp_s[16 + tid] + bhh[2 * HH + j]));
            g_kh[j] = (1.f - z) * n2 + z * kh_s[j];
        }
        kgrid_barrier((unsigned)(t + 1));
    }

    for (int i = tid; i < HH; i += 256) kh_s[i] = __ldcg(&g_kh[i]);
    __syncthreads();
    {
        int j = j0 + w;
        const float* wr = Wg + (size_t)j * HH;
        float a = 0.f;
        for (int k = lane; k < HH; k += 32) a += wr[k] * kh_s[k];
#pragma unroll
        for (int o = 16; o; o >>= 1) a += __shfl_xor_sync(0xffffffffu, a, o);
        if (lane == 0) g_gate[j] = sigm(a + bg[j]);
    }
}

// ---------------- persistent HMMA recurrence (k-split 2-group, fp16 2-pass) ------
// 128 blocks x 512 threads (16 warps = 2 groups of 8). Group g owns chunks
// [8g, 8g+8) with its own 2-stage pipeline, mbarriers and named barrier. Per
// k32 block: 3 B-LDSM + 4 A-LDSM, 12 MMAs. End of step: group 1 publishes
// partials via padded SMEM; group 0 merges + epilogue. Doubles schedulable
// warps (occ 12.5% -> 25%) to cover the exposed latency chains.
__global__ void __launch_bounds__(RTH, 1)
recur_kernel(const float* __restrict__ Whh, const float* __restrict__ bhh,
             float* __restrict__ out) {
    extern __shared__ char smem[];
    uint32_t smem_base = smem_to_u32(smem);
    float* bias_s = (float*)(smem + SM_BIAS);
    float* gate_s = (float*)(smem + SM_GATE);
    float* part_s = (float*)(smem + SM_PART);
    __half* wf_s = (__half*)(smem + SM_WF);

    int tid = threadIdx.x;
    int g = tid >> 8;                 // group 0 or 1
    int tloc = tid & 255;             // thread within group
    int lane = tid & 31;
    int wloc = tloc >> 5;             // warp within group (0..7)
    int j0 = blockIdx.x * 8;
    int cbase = g * 8;                // first chunk of this group

    if (tid == 0) {
#pragma unroll
        for (int s = 0; s < 4; ++s) MBARRIER_INIT(smem_base + SM_MBAR + s * 8, 1);
    }
    asm volatile("fence.proxy.async.shared::cta;" ::: "memory");

    // W_hh slice: rows n = gate*8 + cj, k-contiguous fp16, row stride 1032
    for (int idx = tid; idx < 24 * HH; idx += RTH) {
        int n = idx >> 10, k = idx & (HH - 1);
        float f = Whh[(size_t)((n >> 3) * HH + j0 + (n & 7)) * HH + k];
        wf_s[n * 1032 + k] = __float2half_rn(f);
    }
    if (tid < 24) bias_s[tid] = bhh[(tid >> 3) * HH + j0 + (tid & 7)];
    if (tid < 8)  gate_s[tid] = g_gate[j0 + tid];
    __syncthreads();

    // fragment geometry (per group; same m16 tiling)
    int arow = 16 * wloc + (lane & 15);
    int ar7 = arow & 7;
    uint32_t arowb = (uint32_t)(arow * 128);
    int lhalf = lane >> 4;
    uint32_t b_off[3];
#pragma unroll
    for (int nt = 0; nt < 3; ++nt)
        b_off[nt] = (uint32_t)((nt * 8 + (lane & 7)) * 2064 + (lane >> 3) * 16);

    int row0 = 16 * wloc + (lane >> 2);
    int jc = 2 * (lane & 3);
    float gv = gate_s[jc], gv1 = gate_s[jc + 1];
    float b_r0 = bias_s[jc],      b_r1 = bias_s[jc + 1];
    float b_z0 = bias_s[8 + jc],  b_z1 = bias_s[8 + jc + 1];
    float b_n0 = bias_s[16 + jc], b_n1 = bias_s[16 + jc + 1];

    int mychunk = j0 >> 6;
    int cw = (j0 & 63) + jc;
    uint32_t ep0 = (uint32_t)(((row0 * 128 + cw * 2) ^ ((row0 & 7) << 4)));
    uint32_t ep1 = (uint32_t)((((row0 + 8) * 128 + cw * 2) ^ (((row0 + 8) & 7) << 4)));

    unsigned phbits = 0;              // 2 bits, this group's stages
    uint32_t mb_base = smem_base + SM_MBAR + (uint32_t)(2 * g) * 8;
    uint32_t stg_base = smem_base + SM_A + (uint32_t)(2 * g) * CHKB;

#pragma unroll 1
    for (int t = 0; t < TT; ++t) {
        int sel = t & 1;
        const char* hsrc = (const char*)&g_hpk[sel][0][0][0][0];
        char* hdst = (char*)&g_hpk[sel ^ 1][0][0][0][0];
        const float* xp = g_xproj + (size_t)t * BB * H3;

        // prologue: this group's issuer fills its 2 stages
        if (tloc == 0) {
#pragma unroll
            for (int p = 0; p < 2; ++p) {
                uint32_t mb = mb_base + p * 8;
                MBAR_ARRIVE_EXPECT(mb, CHKB);
                BULK_G2S(stg_base + p * CHKB, hsrc + (size_t)(cbase + p) * CHKB, CHKB, mb);
            }
        }

        // epilogue inputs (group 0 only)
        float2 xr0, xz0, xn0, xr1, xz1, xn1;
        float hold00 = 0.f, hold01 = 0.f, hold10 = 0.f, hold11 = 0.f;
        if (g == 0) {
            const float* xpr0 = xp + (size_t)row0 * H3 + j0 + jc;
            const float* xpr1 = xp + (size_t)(row0 + 8) * H3 + j0 + jc;
            xr0 = __ldcs((const float2*)(xpr0));
            xz0 = __ldcs((const float2*)(xpr0 + HH));
            xn0 = __ldcs((const float2*)(xpr0 + 2 * HH));
            xr1 = __ldcs((const float2*)(xpr1));
            xz1 = __ldcs((const float2*)(xpr1 + HH));
            xn1 = __ldcs((const float2*)(xpr1 + 2 * HH));
            const char* hcs = hsrc + (size_t)mychunk * CHKB;
            __half2 hh0 = *(const __half2*)(hcs + ep0);
            __half2 hl0 = *(const __half2*)(hcs + 16384 + ep0);
            __half2 hh1 = *(const __half2*)(hcs + ep1);
            __half2 hl1 = *(const __half2*)(hcs + 16384 + ep1);
            hold00 = __low2float(hh0) + __low2float(hl0);
            hold01 = __high2float(hh0) + __high2float(hl0);
            hold10 = __low2float(hh1) + __low2float(hl1);
            hold11 = __high2float(hh1) + __high2float(hl1);
        }

        float cacc[3][2][4];
#pragma unroll
        for (int nt = 0; nt < 3; ++nt)
#pragma unroll
            for (int s = 0; s < 2; ++s)
#pragma unroll
                for (int i = 0; i < 4; ++i) cacc[nt][s][i] = 0.f;

#pragma unroll 1
        for (int cc = 0; cc < 8; ++cc) {
            int c = cbase + cc;
            int stg = cc & 1;
            uint32_t mb = mb_base + stg * 8;
            MBARRIER_WAIT_PARITY(mb, (phbits >> stg) & 1);
            phbits ^= (1u << stg);

            uint32_t sbase = stg_base + (uint32_t)(stg * CHKB) + arowb;
#pragma unroll
            for (int s2 = 0; s2 < 2; ++s2) {
                uint32_t bf[3][4];
#pragma unroll
                for (int nt = 0; nt < 3; ++nt) {
                    uint32_t bb = smem_base + b_off[nt] + (uint32_t)(c * 128 + s2 * 64);
                    LDSM_X4(bf[nt][0], bf[nt][1], bf[nt][2], bf[nt][3], bb + SM_WF);
                }
                uint32_t ah[2][4], al[2][4];
#pragma unroll
                for (int s = 0; s < 2; ++s) {
                    int u = s2 * 4 + s * 2 + lhalf;
                    uint32_t aa = sbase + (uint32_t)(((u ^ ar7)) << 4);
                    LDSM_X4(ah[s][0], ah[s][1], ah[s][2], ah[s][3], aa);
                    LDSM_X4(al[s][0], al[s][1], al[s][2], al[s][3], aa + 16384);
                }
#pragma unroll
                for (int s = 0; s < 2; ++s)
#pragma unroll
                    for (int nt = 0; nt < 3; ++nt)
                        MMA16816(cacc[nt][s], ah[s], bf[nt][2 * s], bf[nt][2 * s + 1]);
#pragma unroll
                for (int s = 0; s < 2; ++s)
#pragma unroll
                    for (int nt = 0; nt < 3; ++nt)
                        MMA16816(cacc[nt][s], al[s], bf[nt][2 * s], bf[nt][2 * s + 1]);
            }
            NAMED_BAR(1 + g, 256);    // group-local: all warps done with this stage

            if (cc + 2 < 8 && tloc == 0) {
                MBAR_ARRIVE_EXPECT(mb, CHKB);
                BULK_G2S(stg_base + (uint32_t)(stg * CHKB),
                         hsrc + (size_t)(c + 2) * CHKB, CHKB, mb);
            }
        }

        // merge k-parity accumulators
        float cfin[3][4];
#pragma unroll
        for (int nt = 0; nt < 3; ++nt)
#pragma unroll
            for (int i = 0; i < 4; ++i) cfin[nt][i] = cacc[nt][0][i] + cacc[nt][1][i];

        // group 1 publishes partials; group 0 merges + epilogue
        if (g == 1) {
#pragma unroll
            for (int nt = 0; nt < 3; ++nt)
#pragma unroll
                for (int i = 0; i < 4; ++i)
                    part_s[tloc * 13 + nt * 4 + i] = cfin[nt][i];
        }
        __syncthreads();

        if (g == 0) {
#pragma unroll
            for (int nt = 0; nt < 3; ++nt)
#pragma unroll
                for (int i = 0; i < 4; ++i)
                    cfin[nt][i] += part_s[tloc * 13 + nt * 4 + i];

            char* hcd = hdst + (size_t)mychunk * CHKB;
#pragma unroll
            for (int half = 0; half < 2; ++half) {
                int row = row0 + half * 8;
                int ib = 2 * half;
                float xr_ = half ? xr1.x : xr0.x, xr_1 = half ? xr1.y : xr0.y;
                float xz_ = half ? xz1.x : xz0.x, xz_1 = half ? xz1.y : xz0.y;
                float xn_ = half ? xn1.x : xn0.x, xn_1 = half ? xn1.y : xn0.y;
                float ho0 = half ? hold10 : hold00;
                float ho1 = half ? hold11 : hold01;

                float rg0 = sigm(xr_ + cfin[0][ib] + b_r0);
                float zg0 = sigm(xz_ + cfin[1][ib] + b_z0);
                float ng0 = tanh_fast(xn_ + rg0 * (cfin[2][ib] + b_n0));
                float o0 = gv * ((1.f - zg0) * ng0 + zg0 * ho0);

                float rg1 = sigm(xr_1 + cfin[0][ib + 1] + b_r1);
                float zg1 = sigm(xz_1 + cfin[1][ib + 1] + b_z1);
                float ng1 = tanh_fast(xn_1 + rg1 * (cfin[2][ib + 1] + b_n1));
                float o1 = gv1 * ((1.f - zg1) * ng1 + zg1 * ho1);

                if (t == TT - 1) {
                    *(float2*)(out + (size_t)row * HH + j0 + jc) = make_float2(o0, o1);
                } else {
                    __half h0 = __float2half_rn(o0);
                    __half h1 = __float2half_rn(o1);
                    __half2 hv; hv.x = h0; hv.y = h1;
                    __half2 lv;
                    lv.x = __float2half_rn(o0 - __half2float(h0));
                    lv.y = __float2half_rn(o1 - __half2float(h1));
                    uint32_t ep = half ? ep1 : ep0;
                    *(__half2*)(hcd + ep) = hv;
                    *(__half2*)(hcd + 16384 + ep) = lv;
                }
            }
        }

        if (t < TT - 1) grid_barrier((unsigned)(t + 1));
    }
}

// ---------------- launch ---------------------------------------------------------
extern "C" void kernel_launch(void* const* d_in, const int* in_sizes, int n_in,
                              void* d_out, int out_size) {
    const int* x        = (const int*)d_in[0];
    const int* key_ids  = (const int*)d_in[1];
    const float* emb    = (const float*)d_in[2];
    const float* W_ih   = (const float*)d_in[3];
    const float* W_hh   = (const float*)d_in[4];
    const float* b_ih   = (const float*)d_in[5];
    const float* b_hh   = (const float*)d_in[6];
    const float* W_g    = (const float*)d_in[7];
    const float* b_g    = (const float*)d_in[8];
    float* out = (float*)d_out;

    cudaFuncSetAttribute(recur_kernel, cudaFuncAttributeMaxDynamicSharedMemorySize, SM_TOTAL);
    cudaFuncSetAttribute(keyall_kernel, cudaFuncAttributeMaxDynamicSharedMemorySize, KA_TOTAL);

    // recur stays at launch index 3 (ncu -s 5 with harness offset 2 profiles it)
    zero_kernel<<<(BB * HH + 255) / 256, 256>>>();                               // 0
    keyall_kernel<<<NBLK, 256, KA_TOTAL>>>(key_ids, emb, W_ih, W_hh,
                                           b_ih, b_hh, W_g, b_g);                // 1
    dim3 xg(H3 / XBN, (BB * TT) / XBM);
    xproj_kernel<<<xg, 256>>>(x, emb, W_ih, b_ih);                               // 2
    recur_kernel<<<NBLK, RTH, SM_TOTAL>>>(W_hh, b_hh, out);                      // 3
    pad_kernel<<<1, 32>>>();                                                     // 4
    pad_kernel<<<1, 32>>>();                                                     // 5
}